// round 6
// baseline (speedup 1.0000x reference)
#include <cuda_runtime.h>
#include <math.h>

#define BB   8
#define NN   107136
#define PRE  2048
#define POST 128
#define CAND 4096
#define WPB  32      // 64-bit words per row mask (PRE/64)
#define HB   65536   // 16-bit histogram bins
#define NB   128     // persistent CTAs (<= SM count, all co-resident)
#define T    1024    // threads per CTA

typedef unsigned long long ull;

// ---------------- scratch (static __device__, no allocations) ----------------
static __device__ unsigned g_skey[BB * NN];
static __device__ unsigned g_hist16[BB * HB];
static __device__ unsigned g_thresh[BB];          // 0/1 both mean "take all"
static __device__ ull      g_cand[BB * CAND];
static __device__ int      g_cand_cnt[BB];
static __device__ ull      g_topkeys[BB * PRE];
static __device__ float    g_boxes[BB * PRE * 7];
static __device__ float4   g_bb4[BB * PRE];
static __device__ int      g_dl[BB * PRE];
static __device__ ull      g_supmask[(size_t)BB * PRE * WPB];
static __device__ ull      g_validmask[BB * WPB];
static __device__ unsigned g_bar_count;
static __device__ volatile unsigned g_bar_release;

// ---------------- software grid barrier (sense-reversing) ----------------
__device__ __forceinline__ void grid_sync(unsigned& sense) {
    __syncthreads();
    if (threadIdx.x == 0) {
        sense ^= 1u;
        __threadfence();
        if (atomicAdd(&g_bar_count, 1u) == NB - 1) {
            g_bar_count = 0;
            __threadfence();
            g_bar_release = sense;
        } else {
            while (g_bar_release != sense) { }
        }
        __threadfence();
    }
    __syncthreads();
}

// ---------------- the single persistent kernel ----------------
__global__ void __launch_bounds__(T, 1) mega_kernel(
    const float* __restrict__ boxp,
    const float4* __restrict__ cls4,
    const float* __restrict__ dirp,
    const float* __restrict__ anch,
    float* __restrict__ out)
{
    const int cta = blockIdx.x;
    const int tid = threadIdx.x;
    unsigned sense = g_bar_release;   // safe: can't change before this CTA's first arrival

    __shared__ __align__(16) unsigned char s_u[32768];   // phase-exclusive union
    __shared__ ull s_keep[WPB];
    __shared__ int s_sel[POST];
    __shared__ int s_misc[2];

    // ===== Phase A: softmax scores -> keys + 16-bit histogram =====
    {
        const int P = BB * NN / 2;
        for (int i = cta * T + tid; i < P; i += NB * T) {
            int b = (2 * i) / NN;
            float4 c = cls4[i];
            float m0 = fmaxf(c.x, c.y);
            float p0 = expf(c.y - m0) / (expf(c.x - m0) + expf(c.y - m0));
            float m1 = fmaxf(c.z, c.w);
            float p1 = expf(c.w - m1) / (expf(c.z - m1) + expf(c.w - m1));
            unsigned k0 = (p0 >= 0.05f) ? __float_as_uint(p0) : 0u;
            unsigned k1 = (p1 >= 0.05f) ? __float_as_uint(p1) : 0u;
            ((uint2*)g_skey)[i] = make_uint2(k0, k1);
            if (k0) atomicAdd(&g_hist16[b * HB + (k0 >> 16)], 1u);
            if (k1) atomicAdd(&g_hist16[b * HB + (k1 >> 16)], 1u);
        }
    }
    grid_sync(sense);

    // ===== Phase B: parallel crossing-bin search (CTAs 0..7) =====
    if (cta < BB) {
        int b = cta;
        int lane = tid & 31, wid = tid >> 5;
        unsigned* wsum = (unsigned*)s_u;
        unsigned* wsuf = (unsigned*)s_u + 32;
        const uint4* h4 = (const uint4*)(g_hist16 + b * HB);
        unsigned tsum = 0;
#pragma unroll
        for (int j = 0; j < 16; ++j) {
            uint4 v = h4[tid * 16 + j];
            tsum += v.x + v.y + v.z + v.w;
        }
        unsigned s = tsum;
#pragma unroll
        for (int off = 1; off < 32; off <<= 1) {
            unsigned o = __shfl_down_sync(0xFFFFFFFFu, s, off);
            if (lane + off < 32) s += o;
        }
        if (lane == 0) wsum[wid] = s;
        __syncthreads();
        if (tid < 32) {
            unsigned t = wsum[tid];
            unsigned e = t;
#pragma unroll
            for (int off = 1; off < 32; off <<= 1) {
                unsigned o = __shfl_down_sync(0xFFFFFFFFu, e, off);
                if (tid + off < 32) e += o;
            }
            wsuf[tid] = e - t;
        }
        __syncthreads();
        unsigned above = wsuf[wid] + (s - tsum);
        if (above < PRE && above + tsum >= PRE) {
            unsigned run = above;
            int found = -1;
            for (int j = 15; j >= 0 && found < 0; --j) {
                uint4 v = h4[tid * 16 + j];
                unsigned a[4] = {v.x, v.y, v.z, v.w};
                for (int q = 3; q >= 0; --q) {
                    if (run + a[q] >= PRE) { found = tid * 64 + j * 4 + q; break; }
                    run += a[q];
                }
            }
            g_thresh[b] = ((unsigned)found) << 16;
        }
    }
    grid_sync(sense);

    // ===== Phase C: compact candidates (vec4 + warp-aggregated atomic) =====
    {
        const int Q = BB * NN / 4;
        for (int i4 = cta * T + tid; i4 < Q; i4 += NB * T) {
            int e0 = i4 * 4;
            int b = e0 / NN;                     // NN % 128 == 0 -> warp-uniform
            unsigned thresh = g_thresh[b];
            uint4 kv = ((const uint4*)g_skey)[i4];
            unsigned k[4] = {kv.x, kv.y, kv.z, kv.w};
            ull loc[4]; int nh = 0;
            unsigned base_i = (unsigned)(e0 - b * NN);
#pragma unroll
            for (int q = 0; q < 4; ++q) {
                if (k[q] && k[q] >= thresh)
                    loc[nh++] = ((ull)k[q] << 32) |
                                (ull)(0xFFFFFFFFu - (base_i + q));
            }
            int lane = tid & 31;
            int pre = nh;
#pragma unroll
            for (int off = 1; off < 32; off <<= 1) {
                int o = __shfl_up_sync(0xFFFFFFFFu, pre, off);
                if (lane >= off) pre += o;
            }
            int tot = __shfl_sync(0xFFFFFFFFu, pre, 31);
            pre -= nh;
            int base = 0;
            if (lane == 31 && tot > 0) base = atomicAdd(&g_cand_cnt[b], tot);
            base = __shfl_sync(0xFFFFFFFFu, base, 31);
            for (int q = 0; q < nh; ++q) {
                int p = base + pre + q;
                if (p < CAND) g_cand[b * CAND + p] = loc[q];
            }
        }
    }
    grid_sync(sense);

    // ===== Phase D: rank-scatter exact top-2048 (48 CTAs: 8 batches x 4 subs... 6 subs) =====
    if (cta < 48) {
        int b = cta / 6, sub = cta % 6;          // sub covers i in [sub*1024, sub*1024+1023]
        ull* sk = (ull*)s_u;                     // 32KB candidate cache
        int cnt = g_cand_cnt[b]; if (cnt > CAND) cnt = CAND;
        for (int j = tid; j < cnt; j += T) sk[j] = g_cand[b * CAND + j];
        __syncthreads();
        int i = sub * T + tid;
        if (i < cnt) {
            ull mine = sk[i];
            int rank = 0, j = 0;
            for (; j + 4 <= cnt; j += 4) {
                rank += (sk[j]     > mine);
                rank += (sk[j + 1] > mine);
                rank += (sk[j + 2] > mine);
                rank += (sk[j + 3] > mine);
            }
            for (; j < cnt; ++j) rank += (sk[j] > mine);
            if (rank < PRE) g_topkeys[(size_t)b * PRE + rank] = mine;
        }
    }
    grid_sync(sense);

    // ===== Phase E: decode selected boxes =====
    {
        int i = cta * T + tid;
        if (i < BB * PRE) {
            int b = i / PRE, r = i % PRE;
            ull key = g_topkeys[i];
            unsigned skey = (unsigned)(key >> 32);
            float o[7] = {0.f, 0.f, 0.f, 0.f, 0.f, 0.f, 0.f};
            float4 bb = make_float4(0.f, 0.f, 0.f, 0.f);
            int dl = 0;
            if (skey) {
                unsigned idx = 0xFFFFFFFFu - (unsigned)(key & 0xFFFFFFFFull);
                size_t base = ((size_t)b * NN + idx) * 7;
                float xa = anch[base + 0], ya = anch[base + 1], za = anch[base + 2];
                float wa = anch[base + 3], la = anch[base + 4], ha = anch[base + 5];
                float ra = anch[base + 6];
                float xt = boxp[base + 0], yt = boxp[base + 1], zt = boxp[base + 2];
                float wt = boxp[base + 3], lt = boxp[base + 4], ht = boxp[base + 5];
                float rt = boxp[base + 6];
                za = za + ha * 0.5f;
                float diag = sqrtf(la * la + wa * wa);
                float xg = xt * diag + xa;
                float yg = yt * diag + ya;
                float zg = zt * ha + za;
                float lg = expf(lt) * la;
                float wg = expf(wt) * wa;
                float hg = expf(ht) * ha;
                float rg = rt + ra;
                zg = zg - hg * 0.5f;
                o[0] = xg; o[1] = yg; o[2] = zg; o[3] = wg; o[4] = lg; o[5] = hg; o[6] = rg;
                float cc = fabsf(cosf(rg)), ss = fabsf(sinf(rg));
                float hx = 0.5f * (wg * cc + lg * ss);
                float hy = 0.5f * (wg * ss + lg * cc);
                bb = make_float4(xg - hx, yg - hy, xg + hx, yg + hy);
                size_t dbase = ((size_t)b * NN + idx) * 2;
                dl = (dirp[dbase + 1] > dirp[dbase + 0]) ? 1 : 0;
                atomicOr(&g_validmask[b * WPB + (r >> 6)], 1ull << (r & 63));
            }
#pragma unroll
            for (int j = 0; j < 7; ++j) g_boxes[(size_t)i * 7 + j] = o[j];
            g_bb4[i] = bb;
            g_dl[i] = dl;
        }
    }
    grid_sync(sense);

    // ===== Phase F: pairwise IoU bit-matrix (4224 tile-tasks, 4/CTA/iter) =====
    {
        const int NTASK = 528 * BB;
        int grp = tid >> 8;        // 4 groups of 256 threads
        int t2  = tid & 255;
        float4* scol = (float4*)(s_u + grp * 2560);
        float*  sca  = (float*) (s_u + grp * 2560 + 1024);
        float4* srow = (float4*)(s_u + grp * 2560 + 1280);
        float*  sra  = (float*) (s_u + grp * 2560 + 2304);
        for (int base = 0; base < NTASK; base += NB * 4) {
            int task = base + cta * 4 + grp;
            bool active = (task < NTASK);
            int rb = 0, cb = 0, b = 0;
            if (active) {
                int p = task % 528;
                b = task / 528;
                rb = (int)((65.0f - sqrtf(4225.0f - 8.0f * (float)p)) * 0.5f);
                while (rb * (65 - rb) / 2 > p) --rb;
                while ((rb + 1) * (64 - rb) / 2 <= p) ++rb;
                cb = rb + (p - rb * (65 - rb) / 2);
                if (t2 < 64) {
                    float4 c = g_bb4[(size_t)b * PRE + cb * 64 + t2];
                    scol[t2] = c; sca[t2] = (c.z - c.x) * (c.w - c.y);
                } else if (t2 < 128) {
                    int r = t2 - 64;
                    float4 c = g_bb4[(size_t)b * PRE + rb * 64 + r];
                    srow[r] = c; sra[r] = (c.z - c.x) * (c.w - c.y);
                }
            }
            __syncthreads();
            if (active) {
                int wid2 = t2 >> 5, lane = t2 & 31;
#pragma unroll
                for (int rr = 0; rr < 8; ++rr) {
                    int r = wid2 * 8 + rr;
                    int grow = rb * 64 + r;
                    float4 rbx = srow[r];
                    float  ra  = sra[r];
                    ull bits = 0ull;
#pragma unroll
                    for (int h = 0; h < 2; ++h) {
                        int c = h * 32 + lane;
                        int gcol = cb * 64 + c;
                        float4 cc = scol[c];
                        float ix = fmaxf(0.f, fminf(rbx.z, cc.z) - fmaxf(rbx.x, cc.x));
                        float iy = fmaxf(0.f, fminf(rbx.w, cc.w) - fmaxf(rbx.y, cc.y));
                        float inter = ix * iy;
                        float denom = fmaxf(ra + sca[c] - inter, 1e-8f);
                        bool sup = (gcol > grow) && (inter > 0.5f * denom);
                        unsigned m = __ballot_sync(0xFFFFFFFFu, sup);
                        bits |= (ull)m << (h * 32);
                    }
                    if (lane == 0)
                        g_supmask[((size_t)b * PRE + grow) * WPB + cb] = bits;
                }
            }
            __syncthreads();
        }
    }
    grid_sync(sense);

    // ===== Phase G: greedy NMS + final output (CTAs 0..7) =====
    if (cta < BB) {
        int b = cta;
        ull (*s_rows)[64][WPB] = (ull (*)[64][WPB])s_u;   // 2 x 16KB
        int lane = tid & 31;
        ull remv = 0ull, myvalid = 0ull;
        if (tid < 32) myvalid = g_validmask[b * WPB + tid];

        for (int idx = tid; idx < 64 * WPB; idx += T) {
            int r = idx >> 5, w = idx & 31;
            s_rows[0][r][w] = g_supmask[((size_t)b * PRE + r) * WPB + w];
        }
        __syncthreads();

        for (int chunk = 0; chunk < WPB; ++chunk) {
            int cur = chunk & 1;
            if (tid >= 32 && chunk + 1 < WPB) {          // 992 prefetch threads
                int base = (chunk + 1) * 64;
                for (int idx = tid - 32; idx < 64 * WPB; idx += T - 32) {
                    int r = idx >> 5, w = idx & 31;
                    s_rows[cur ^ 1][r][w] = g_supmask[((size_t)b * PRE + base + r) * WPB + w];
                }
            }
            if (tid < 32) {
                ull alive = 0ull;
                if (lane == chunk) {
                    ull w = remv, vw = myvalid;
#pragma unroll
                    for (int g = 0; g < 4; ++g) {
                        ull sd[16];
#pragma unroll
                        for (int j = 0; j < 16; ++j) sd[j] = s_rows[cur][g * 16 + j][chunk];
#pragma unroll
                        for (int j = 0; j < 16; ++j) {
                            ull bit = 1ull << (g * 16 + j);
                            if ((vw & bit) && !(w & bit)) { alive |= bit; w |= sd[j]; }
                        }
                    }
                    remv = w;
                    s_keep[chunk] = alive;
                }
                alive = __shfl_sync(0xFFFFFFFFu, alive, chunk);
                if (lane > chunk) {
                    ull m = alive;
                    while (m) {
                        int r = __ffsll((long long)m) - 1;
                        m &= m - 1;
                        remv |= s_rows[cur][r][lane];
                    }
                }
            }
            __syncthreads();
        }

        // ---- fused output ----
        if (tid == 0) {
            int cnt = 0;
            for (int w = 0; w < WPB && cnt < POST; ++w) {
                ull m = s_keep[w];
                while (m && cnt < POST) {
                    int r = __ffsll((long long)m) - 1;
                    m &= m - 1;
                    s_sel[cnt++] = w * 64 + r;
                }
            }
            s_misc[0] = cnt;
        }
        __syncthreads();

        if (tid < POST) {
            float o0 = 0.f, o1 = 0.f, o2 = 0.f, o3 = 0.f, o4 = 0.f, o5 = 0.f, o6 = 0.f;
            float os = 0.f, om = 0.f;
            if (tid < s_misc[0]) {
                int r = s_sel[tid];
                const float* bx = &g_boxes[((size_t)b * PRE + r) * 7];
                float x = bx[0], y = bx[1], z = bx[2];
                float w = bx[3], l = bx[4], h = bx[5], rg = bx[6];
                float score = __uint_as_float((unsigned)(g_topkeys[(size_t)b * PRE + r] >> 32));
                int dl = g_dl[b * PRE + r];
                const float period = 3.14159265358979323846f;
                float dir_rot = rg - floorf(rg / period) * period;
                float new_r = dir_rot + period * (float)dl;
                bool in_range = (x >= 0.0f) && (y >= -39.68f) && (z >= -5.0f) &&
                                (x <= 69.12f) && (y <= 39.68f) && (z <= 5.0f);
                if (in_range) {
                    o0 = x; o1 = y; o2 = z; o3 = w; o4 = l; o5 = h; o6 = new_r;
                    os = score; om = 1.0f;
                }
            }
            size_t bo = (size_t)b * POST + tid;
            out[bo * 7 + 0] = o0; out[bo * 7 + 1] = o1; out[bo * 7 + 2] = o2;
            out[bo * 7 + 3] = o3; out[bo * 7 + 4] = o4; out[bo * 7 + 5] = o5;
            out[bo * 7 + 6] = o6;
            out[BB * POST * 7 + bo]                 = os;   // scores
            out[BB * POST * 7 + BB * POST + bo]     = 0.0f; // labels
            out[BB * POST * 7 + 2 * BB * POST + bo] = om;   // mask
        }
    }
    grid_sync(sense);

    // ===== Phase H: cleanup for next replay (state restored to zeros) =====
    {
        int i = cta * T + tid;
        if (i < BB * HB / 4) ((uint4*)g_hist16)[i] = make_uint4(0u, 0u, 0u, 0u);
        if (i < BB) { g_cand_cnt[i] = 0; g_thresh[i] = 0u; }
        if (i < BB * WPB) g_validmask[i] = 0ull;
        if (i < BB * PRE) g_topkeys[i] = 0ull;
    }
}

// ---------------- launcher: ONE kernel ----------------
extern "C" void kernel_launch(void* const* d_in, const int* in_sizes, int n_in,
                              void* d_out, int out_size) {
    const float* boxp = (const float*)d_in[0];   // (B,N,7)
    const float* clsp = (const float*)d_in[1];   // (B,N,2)
    const float* dirp = (const float*)d_in[2];   // (B,N,2)
    const float* anch = (const float*)d_in[3];   // (B,N,7)
    float* out = (float*)d_out;

    mega_kernel<<<NB, T>>>(boxp, (const float4*)clsp, dirp, anch, out);
}

// round 7
// speedup vs baseline: 2.2591x; 2.2591x over previous
#include <cuda_runtime.h>
#include <math.h>

#define BB   8
#define NN   107136
#define PRE  2048
#define POST 128
#define CAND 6144    // crossing 16-bit bin is wide near p~1: cnt ~4600
#define WPB  32      // 64-bit words per row mask (PRE/64)
#define HB   65536   // 16-bit histogram bins

typedef unsigned long long ull;

// ---------------- scratch (static __device__, no allocations) ----------------
static __device__ unsigned g_skey[BB * NN];
static __device__ unsigned g_hist16[BB * HB];
static __device__ unsigned g_thresh[BB];
static __device__ ull      g_cand[BB * CAND];
static __device__ int      g_cand_cnt[BB];
static __device__ ull      g_topkeys[BB * PRE];
static __device__ float    g_boxes[BB * PRE * 7];
static __device__ float4   g_bb4[BB * PRE];
static __device__ int      g_dl[BB * PRE];
static __device__ ull      g_supmask[(size_t)BB * PRE * WPB];
static __device__ ull      g_validmask[BB * WPB];

// ---------------- 0) zero scratch ----------------
__global__ void zero_kernel() {
    int i = blockIdx.x * blockDim.x + threadIdx.x;
    if (i < BB * HB / 4) ((uint4*)g_hist16)[i] = make_uint4(0u, 0u, 0u, 0u);
    if (i < BB) { g_cand_cnt[i] = 0; g_thresh[i] = 1u; }
    if (i < BB * WPB) g_validmask[i] = 0ull;
    if (i < BB * PRE) g_topkeys[i] = 0ull;
}

// ---------------- 1) scores -> keys + 16-bit histogram (ONE expf/elem) ------
__global__ void score_hist_kernel(const float4* __restrict__ cls) {
    int i = blockIdx.x * blockDim.x + threadIdx.x;   // pair index
    if (i >= BB * NN / 2) return;
    int b = (2 * i) / NN;
    float4 c = cls[i];
    // p = expf(y-m)/(expf(x-m)+expf(y-m)); m=max -> one expf arg is 0, expf(0)=1
    float p0, p1;
    {
        float d = c.y - c.x;
        if (d <= 0.0f) { float e = expf(d);  p0 = e / (1.0f + e); }
        else           { float e = expf(-d); p0 = 1.0f / (e + 1.0f); }
    }
    {
        float d = c.w - c.z;
        if (d <= 0.0f) { float e = expf(d);  p1 = e / (1.0f + e); }
        else           { float e = expf(-d); p1 = 1.0f / (e + 1.0f); }
    }
    unsigned k0 = (p0 >= 0.05f) ? __float_as_uint(p0) : 0u;
    unsigned k1 = (p1 >= 0.05f) ? __float_as_uint(p1) : 0u;
    ((uint2*)g_skey)[i] = make_uint2(k0, k1);
    if (k0) atomicAdd(&g_hist16[b * HB + (k0 >> 16)], 1u);
    if (k1) atomicAdd(&g_hist16[b * HB + (k1 >> 16)], 1u);
}

// ---------------- 2) parallel crossing-bin search (suffix scan) -------------
__global__ void __launch_bounds__(1024) scan_kernel() {
    int b = blockIdx.x, tid = threadIdx.x;
    int lane = tid & 31, wid = tid >> 5;
    __shared__ unsigned wsum[32];
    __shared__ unsigned wsuf[32];
    const uint4* h4 = (const uint4*)(g_hist16 + b * HB);
    unsigned tsum = 0;
#pragma unroll
    for (int j = 0; j < 16; ++j) {
        uint4 v = h4[tid * 16 + j];
        tsum += v.x + v.y + v.z + v.w;
    }
    unsigned s = tsum;
#pragma unroll
    for (int off = 1; off < 32; off <<= 1) {
        unsigned o = __shfl_down_sync(0xFFFFFFFFu, s, off);
        if (lane + off < 32) s += o;
    }
    if (lane == 0) wsum[wid] = s;
    __syncthreads();
    if (tid < 32) {
        unsigned t = wsum[tid];
        unsigned e = t;
#pragma unroll
        for (int off = 1; off < 32; off <<= 1) {
            unsigned o = __shfl_down_sync(0xFFFFFFFFu, e, off);
            if (tid + off < 32) e += o;
        }
        wsuf[tid] = e - t;
    }
    __syncthreads();
    unsigned above = wsuf[wid] + (s - tsum);
    if (above < PRE && above + tsum >= PRE) {   // unique crossing thread
        unsigned run = above;
        int found = -1;
        for (int j = 15; j >= 0 && found < 0; --j) {
            uint4 v = h4[tid * 16 + j];
            unsigned a[4] = {v.x, v.y, v.z, v.w};
            for (int q = 3; q >= 0; --q) {
                if (run + a[q] >= PRE) { found = tid * 64 + j * 4 + q; break; }
                run += a[q];
            }
        }
        g_thresh[b] = ((unsigned)found) << 16;   // 16-bit bin floor
    }
}

// ---------------- 3) compact candidates (vec4 + warp-aggregated atomic) -----
__global__ void compact_kernel() {
    int i4 = blockIdx.x * blockDim.x + threadIdx.x;
    if (i4 >= BB * NN / 4) return;
    int e0 = i4 * 4;
    int b = e0 / NN;                  // NN % 128 == 0 -> warp-uniform
    unsigned thresh = g_thresh[b];
    uint4 kv = ((const uint4*)g_skey)[i4];
    unsigned k[4] = {kv.x, kv.y, kv.z, kv.w};
    ull loc[4]; int nh = 0;
    unsigned base_i = (unsigned)(e0 - b * NN);
#pragma unroll
    for (int q = 0; q < 4; ++q) {
        if (k[q] && k[q] >= thresh)
            loc[nh++] = ((ull)k[q] << 32) | (ull)(0xFFFFFFFFu - (base_i + q));
    }
    int lane = threadIdx.x & 31;
    int pre = nh;
#pragma unroll
    for (int off = 1; off < 32; off <<= 1) {
        int o = __shfl_up_sync(0xFFFFFFFFu, pre, off);
        if (lane >= off) pre += o;
    }
    int tot = __shfl_sync(0xFFFFFFFFu, pre, 31);
    pre -= nh;
    int base = 0;
    if (lane == 31 && tot > 0) base = atomicAdd(&g_cand_cnt[b], tot);
    base = __shfl_sync(0xFFFFFFFFu, base, 31);
    for (int q = 0; q < nh; ++q) {
        int p = base + pre + q;
        if (p < CAND) g_cand[b * CAND + p] = loc[q];
    }
}

// ---------------- 4) rank-scatter: exact top-2048 order (vectorized) --------
__global__ void __launch_bounds__(256) rank_kernel() {
    int b = blockIdx.y, tid = threadIdx.x;
    __shared__ __align__(16) ull sk[CAND];   // 48KB
    int cnt = g_cand_cnt[b]; if (cnt > CAND) cnt = CAND;
    if (blockIdx.x * 256 >= cnt) return;     // skip fully idle CTAs
    for (int j = tid; j < cnt; j += 256) sk[j] = g_cand[b * CAND + j];
    __syncthreads();
    int i = blockIdx.x * 256 + tid;
    if (i >= cnt) return;
    ull mine = sk[i];
    const ulonglong2* sk2 = (const ulonglong2*)sk;
    int np = cnt >> 1;
    int rank = 0, j = 0;
    for (; j + 2 <= np; j += 2) {
        ulonglong2 a = sk2[j], c = sk2[j + 1];
        rank += (a.x > mine) + (a.y > mine) + (c.x > mine) + (c.y > mine);
    }
    for (; j < np; ++j) {
        ulonglong2 a = sk2[j];
        rank += (a.x > mine) + (a.y > mine);
    }
    if (cnt & 1) rank += (sk[cnt - 1] > mine);
    if (rank < PRE) g_topkeys[(size_t)b * PRE + rank] = mine;
}

// ---------------- 5) decode selected boxes ----------------
__global__ void decode_kernel(const float* __restrict__ boxp,
                              const float* __restrict__ dirp,
                              const float* __restrict__ anch) {
    int i = blockIdx.x * blockDim.x + threadIdx.x;
    if (i >= BB * PRE) return;
    int b = i / PRE, r = i % PRE;
    ull key = g_topkeys[i];
    unsigned skey = (unsigned)(key >> 32);

    float o[7] = {0.f, 0.f, 0.f, 0.f, 0.f, 0.f, 0.f};
    float4 bb = make_float4(0.f, 0.f, 0.f, 0.f);
    int dl = 0;

    if (skey) {
        unsigned idx = 0xFFFFFFFFu - (unsigned)(key & 0xFFFFFFFFull);
        size_t base = ((size_t)b * NN + idx) * 7;
        float xa = anch[base + 0], ya = anch[base + 1], za = anch[base + 2];
        float wa = anch[base + 3], la = anch[base + 4], ha = anch[base + 5];
        float ra = anch[base + 6];
        float xt = boxp[base + 0], yt = boxp[base + 1], zt = boxp[base + 2];
        float wt = boxp[base + 3], lt = boxp[base + 4], ht = boxp[base + 5];
        float rt = boxp[base + 6];

        za = za + ha * 0.5f;
        float diag = sqrtf(la * la + wa * wa);
        float xg = xt * diag + xa;
        float yg = yt * diag + ya;
        float zg = zt * ha + za;
        float lg = expf(lt) * la;
        float wg = expf(wt) * wa;
        float hg = expf(ht) * ha;
        float rg = rt + ra;
        zg = zg - hg * 0.5f;

        o[0] = xg; o[1] = yg; o[2] = zg; o[3] = wg; o[4] = lg; o[5] = hg; o[6] = rg;

        float cc = fabsf(cosf(rg)), ss = fabsf(sinf(rg));
        float hx = 0.5f * (wg * cc + lg * ss);
        float hy = 0.5f * (wg * ss + lg * cc);
        bb = make_float4(xg - hx, yg - hy, xg + hx, yg + hy);

        size_t dbase = ((size_t)b * NN + idx) * 2;
        dl = (dirp[dbase + 1] > dirp[dbase + 0]) ? 1 : 0;

        atomicOr(&g_validmask[b * WPB + (r >> 6)], 1ull << (r & 63));
    }
#pragma unroll
    for (int j = 0; j < 7; ++j) g_boxes[(size_t)i * 7 + j] = o[j];
    g_bb4[i] = bb;
    g_dl[i] = dl;
}

// ---------------- 6) pairwise IoU bit-matrix (upper triangle, ballot) -------
__global__ void __launch_bounds__(256) iou_kernel() {
    int p = blockIdx.x;          // triangular pair index [0, 528)
    int b = blockIdx.y;
    int rb = (int)((65.0f - sqrtf(4225.0f - 8.0f * (float)p)) * 0.5f);
    while (rb * (65 - rb) / 2 > p) --rb;
    while ((rb + 1) * (64 - rb) / 2 <= p) ++rb;
    int cb = rb + (p - rb * (65 - rb) / 2);

    int t = threadIdx.x;
    __shared__ float4 scol[64]; __shared__ float sca[64];
    __shared__ float4 srow[64]; __shared__ float sra[64];
    if (t < 64) {
        float4 c = g_bb4[(size_t)b * PRE + cb * 64 + t];
        scol[t] = c; sca[t] = (c.z - c.x) * (c.w - c.y);
    } else if (t < 128) {
        int r = t - 64;
        float4 c = g_bb4[(size_t)b * PRE + rb * 64 + r];
        srow[r] = c; sra[r] = (c.z - c.x) * (c.w - c.y);
    }
    __syncthreads();

    int wid = t >> 5, lane = t & 31;
#pragma unroll
    for (int rr = 0; rr < 8; ++rr) {
        int r = wid * 8 + rr;
        int grow = rb * 64 + r;
        float4 rbx = srow[r];
        float  ra  = sra[r];
        ull bits = 0ull;
#pragma unroll
        for (int h = 0; h < 2; ++h) {
            int c = h * 32 + lane;
            int gcol = cb * 64 + c;
            float4 cc = scol[c];
            float ix = fmaxf(0.f, fminf(rbx.z, cc.z) - fmaxf(rbx.x, cc.x));
            float iy = fmaxf(0.f, fminf(rbx.w, cc.w) - fmaxf(rbx.y, cc.y));
            float inter = ix * iy;
            float denom = fmaxf(ra + sca[c] - inter, 1e-8f);
            bool sup = (gcol > grow) && (inter > 0.5f * denom);
            unsigned m = __ballot_sync(0xFFFFFFFFu, sup);
            bits |= (ull)m << (h * 32);
        }
        if (lane == 0)
            g_supmask[((size_t)b * PRE + grow) * WPB + cb] = bits;
    }
}

// ---------------- 7) Jacobi-fixpoint greedy NMS + output (exact) ------------
// Greedy NMS == unique fixpoint of K' = valid & ~union_{j in K} M[j][*]
// (M strictly upper-triangular in score order). F is antitone -> F^2 monotone
// -> converges; prefix induction shows the fixpoint is unique (= greedy) and
// no 2-cycles exist. Typically converges in ~3-5 iterations.
__global__ void __launch_bounds__(1024) nms_out_kernel(float* __restrict__ out) {
    int b = blockIdx.x, tid = threadIdx.x;
    int w = tid & 31, rg = tid >> 5;   // word index, 64-row group index
    __shared__ ull s_keep[WPB], s_valid[WPB];
    __shared__ ull s_part[WPB][WPB + 1];
    __shared__ int s_flag;
    __shared__ int s_sel[POST];
    __shared__ int s_cnt;

    if (tid < WPB) {
        ull v = g_validmask[b * WPB + tid];
        s_valid[tid] = v;
        s_keep[tid] = v;
    }
    __syncthreads();

    const ull* rowbase = &g_supmask[((size_t)b * PRE + rg * 64) * WPB + w];

    for (int iter = 0; iter < PRE; ++iter) {
        ull acc = 0ull;
        if (w >= rg) {                      // only upper-triangle words are valid
            ull kw = s_keep[rg];
#pragma unroll 8
            for (int r = 0; r < 64; ++r)
                if ((kw >> r) & 1ull) acc |= rowbase[(size_t)r * WPB];
        }
        s_part[rg][w] = acc;
        if (tid == 0) s_flag = 0;
        __syncthreads();
        if (tid < WPB) {
            ull o = 0ull;
#pragma unroll
            for (int g = 0; g < WPB; ++g) o |= s_part[g][tid];
            ull nk = s_valid[tid] & ~o;
            if (nk != s_keep[tid]) s_flag = 1;
            s_keep[tid] = nk;
        }
        __syncthreads();
        if (!s_flag) break;
    }

    // ---- output: first 128 kept (already in descending score order) ----
    if (tid == 0) {
        int cnt = 0;
        for (int ww = 0; ww < WPB && cnt < POST; ++ww) {
            ull m = s_keep[ww];
            while (m && cnt < POST) {
                int r = __ffsll((long long)m) - 1;
                m &= m - 1;
                s_sel[cnt++] = ww * 64 + r;
            }
        }
        s_cnt = cnt;
    }
    __syncthreads();

    if (tid < POST) {
        float o0 = 0.f, o1 = 0.f, o2 = 0.f, o3 = 0.f, o4 = 0.f, o5 = 0.f, o6 = 0.f;
        float os = 0.f, om = 0.f;
        if (tid < s_cnt) {
            int r = s_sel[tid];
            const float* bx = &g_boxes[((size_t)b * PRE + r) * 7];
            float x = bx[0], y = bx[1], z = bx[2];
            float wd = bx[3], l = bx[4], h = bx[5], rgr = bx[6];
            float score = __uint_as_float((unsigned)(g_topkeys[(size_t)b * PRE + r] >> 32));
            int dl = g_dl[b * PRE + r];
            const float period = 3.14159265358979323846f;   // 2*pi/NUM_DIR_BINS
            float dir_rot = rgr - floorf(rgr / period) * period;
            float new_r = dir_rot + period * (float)dl;
            bool in_range = (x >= 0.0f) && (y >= -39.68f) && (z >= -5.0f) &&
                            (x <= 69.12f) && (y <= 39.68f) && (z <= 5.0f);
            if (in_range) {
                o0 = x; o1 = y; o2 = z; o3 = wd; o4 = l; o5 = h; o6 = new_r;
                os = score; om = 1.0f;
            }
        }
        size_t bo = (size_t)b * POST + tid;
        out[bo * 7 + 0] = o0; out[bo * 7 + 1] = o1; out[bo * 7 + 2] = o2;
        out[bo * 7 + 3] = o3; out[bo * 7 + 4] = o4; out[bo * 7 + 5] = o5;
        out[bo * 7 + 6] = o6;
        out[BB * POST * 7 + bo]                 = os;   // scores
        out[BB * POST * 7 + BB * POST + bo]     = 0.0f; // labels
        out[BB * POST * 7 + 2 * BB * POST + bo] = om;   // mask
    }
}

// ---------------- launcher ----------------
extern "C" void kernel_launch(void* const* d_in, const int* in_sizes, int n_in,
                              void* d_out, int out_size) {
    const float* boxp = (const float*)d_in[0];   // (B,N,7)
    const float* clsp = (const float*)d_in[1];   // (B,N,2)
    const float* dirp = (const float*)d_in[2];   // (B,N,2)
    const float* anch = (const float*)d_in[3];   // (B,N,7)
    float* out = (float*)d_out;

    zero_kernel<<<(BB * HB / 4 + 255) / 256, 256>>>();
    score_hist_kernel<<<(BB * NN / 2 + 255) / 256, 256>>>((const float4*)clsp);
    scan_kernel<<<BB, 1024>>>();
    compact_kernel<<<(BB * NN / 4 + 255) / 256, 256>>>();
    dim3 grank((CAND + 255) / 256, BB);
    rank_kernel<<<grank, 256>>>();
    decode_kernel<<<(BB * PRE + 127) / 128, 128>>>(boxp, dirp, anch);
    dim3 giou(528, BB);
    iou_kernel<<<giou, 256>>>();
    nms_out_kernel<<<BB, 1024>>>(out);
}